// round 1
// baseline (speedup 1.0000x reference)
#include <cuda_runtime.h>
#include <cstdint>

#define N_DIM 16
#define M_DIM 8
#define T_STEPS 50
#define HP 12            // hidden width padded 10 -> 12 (zero-padded weights)
#define BATCH 32768
#define BLOCK 64
#define GRID (BATCH / BLOCK)

#define DT_F 0.01f
#define GAMMA_F 0.1f
#define SIGMA_F 0.2f
// 0.5 * DT * TAU^2
#define LC_SCALE (0.5f * 0.01f * 0.25f)

// ---------------------------------------------------------------------------
// Shared weight block: all rows padded so every row is 16B-aligned and a
// multiple of float4.  Zero-padding makes the padded lanes mathematically
// inert (0-weight, 0-bias contributions).
// ---------------------------------------------------------------------------
struct __align__(16) SW {
    float A[16][16];
    float C[16][16];
    float B[16][8];
    float D[16][8];

    float pW1[17][HP]; float pb1[HP];
    float pW2[HP][HP]; float pb2[HP];
    float pW3[HP][8];  float pb3[8];

    float zW1[17][HP]; float zb1[HP];
    float zW2[HP][HP]; float zb2[HP];
    float zW3[HP][16]; float zb3[16];

    float yW1[16][HP]; float yb1[HP];
    float yW2[HP][HP]; float yb2[HP];
    float yW3[HP][16]; float yb3[16];
};

__device__ float g_partial0[GRID];
__device__ float g_partial1[GRID];

// ---------------------------------------------------------------------------
// helpers
// ---------------------------------------------------------------------------
__device__ __forceinline__ float tanh_fast(float x) {
    float ax = fabsf(x);
    float e  = __expf(-2.0f * ax);          // MUFU.EX2 path, rel err ~1e-7
    float r  = __fdividef(1.0f - e, 1.0f + e);
    return copysignf(r, x);
}

__device__ __forceinline__ void tanh10(float* h) {
#pragma unroll
    for (int j = 0; j < 10; j++) h[j] = tanh_fast(h[j]);
    h[10] = 0.0f; h[11] = 0.0f;
}

template <int PC>
__device__ __forceinline__ void bias_init(float* acc, const float* b) {
#pragma unroll
    for (int j = 0; j < PC / 4; j++) {
        float4 v = reinterpret_cast<const float4*>(b)[j];
        acc[4 * j + 0] = v.x; acc[4 * j + 1] = v.y;
        acc[4 * j + 2] = v.z; acc[4 * j + 3] = v.w;
    }
}

// acc[j] += sum_i x[i] * W[i][j]    (W row-major with row stride NOUT, NOUT%4==0)
template <int NIN, int NOUT>
__device__ __forceinline__ void gemv_acc(float* acc, const float* x, const float* W) {
#pragma unroll
    for (int i = 0; i < NIN; i++) {
        float xi = x[i];
#pragma unroll
        for (int j = 0; j < NOUT / 4; j++) {
            float4 w = reinterpret_cast<const float4*>(W + i * NOUT)[j];
            acc[4 * j + 0] = fmaf(xi, w.x, acc[4 * j + 0]);
            acc[4 * j + 1] = fmaf(xi, w.y, acc[4 * j + 1]);
            acc[4 * j + 2] = fmaf(xi, w.z, acc[4 * j + 2]);
            acc[4 * j + 3] = fmaf(xi, w.w, acc[4 * j + 3]);
        }
    }
}

// acc[i] += dot(x, W[i][:])         (W row-major [NOUT][NIN], NIN%4==0)
template <int NIN, int NOUT>
__device__ __forceinline__ void dotrows_acc(float* acc, const float* x, const float* W) {
#pragma unroll
    for (int i = 0; i < NOUT; i++) {
        float s = acc[i];
#pragma unroll
        for (int j = 0; j < NIN / 4; j++) {
            float4 w = reinterpret_cast<const float4*>(W + i * NIN)[j];
            s = fmaf(x[4 * j + 0], w.x, s);
            s = fmaf(x[4 * j + 1], w.y, s);
            s = fmaf(x[4 * j + 2], w.z, s);
            s = fmaf(x[4 * j + 3], w.w, s);
        }
        acc[i] = s;
    }
}

__device__ __forceinline__ void copy_pad(float* dst, const float* src,
                                         int rows, int cols, int pcols) {
    int tot = rows * pcols;
    for (int k = threadIdx.x; k < tot; k += blockDim.x) {
        int r = k / pcols;
        int c = k - r * pcols;
        dst[k] = (c < cols) ? src[r * cols + c] : 0.0f;
    }
}

// ---------------------------------------------------------------------------
// main simulation kernel: one thread == one trajectory
// ---------------------------------------------------------------------------
__global__ void __launch_bounds__(BLOCK, 1) sim_kernel(
    const float* __restrict__ dw, const float* __restrict__ X0,
    const float* __restrict__ A,  const float* __restrict__ Bm,
    const float* __restrict__ Cm, const float* __restrict__ Dm,
    const float* __restrict__ pW1, const float* __restrict__ pb1,
    const float* __restrict__ pW2, const float* __restrict__ pb2,
    const float* __restrict__ pW3, const float* __restrict__ pb3,
    const float* __restrict__ zW1, const float* __restrict__ zb1,
    const float* __restrict__ zW2, const float* __restrict__ zb2,
    const float* __restrict__ zW3, const float* __restrict__ zb3,
    const float* __restrict__ yW1, const float* __restrict__ yb1,
    const float* __restrict__ yW2, const float* __restrict__ yb2,
    const float* __restrict__ yW3, const float* __restrict__ yb3)
{
    __shared__ SW s;

    copy_pad(&s.A[0][0],  A,  16, 16, 16);
    copy_pad(&s.C[0][0],  Cm, 16, 16, 16);
    copy_pad(&s.B[0][0],  Bm, 16, 8, 8);
    copy_pad(&s.D[0][0],  Dm, 16, 8, 8);

    copy_pad(&s.pW1[0][0], pW1, 17, 10, HP);
    copy_pad(s.pb1,        pb1, 1, 10, HP);
    copy_pad(&s.pW2[0][0], pW2, 10, 10, HP);   // rows 10,11 never read (h[10..11]==0)
    copy_pad(s.pb2,        pb2, 1, 10, HP);
    copy_pad(&s.pW3[0][0], pW3, 10, 8, 8);
    copy_pad(s.pb3,        pb3, 1, 8, 8);

    copy_pad(&s.zW1[0][0], zW1, 17, 10, HP);
    copy_pad(s.zb1,        zb1, 1, 10, HP);
    copy_pad(&s.zW2[0][0], zW2, 10, 10, HP);
    copy_pad(s.zb2,        zb2, 1, 10, HP);
    copy_pad(&s.zW3[0][0], zW3, 10, 16, 16);
    copy_pad(s.zb3,        zb3, 1, 16, 16);

    copy_pad(&s.yW1[0][0], yW1, 16, 10, HP);
    copy_pad(s.yb1,        yb1, 1, 10, HP);
    copy_pad(&s.yW2[0][0], yW2, 10, 10, HP);
    copy_pad(s.yb2,        yb2, 1, 10, HP);
    copy_pad(&s.yW3[0][0], yW3, 10, 16, 16);
    copy_pad(s.yb3,        yb3, 1, 16, 16);

    __syncthreads();

    const int b = blockIdx.x * BLOCK + threadIdx.x;

    float X[16], Y[16];
#pragma unroll
    for (int j = 0; j < 4; j++) {
        float4 v = reinterpret_cast<const float4*>(X0 + b * 16)[j];
        X[4 * j + 0] = v.x; X[4 * j + 1] = v.y;
        X[4 * j + 2] = v.z; X[4 * j + 3] = v.w;
    }

    // ---- Y = MLP_Y0(X0) ----
    {
        float h1[HP];
        bias_init<HP>(h1, s.yb1);
        gemv_acc<16, HP>(h1, X, &s.yW1[0][0]);
        tanh10(h1);
        float h2[HP];
        bias_init<HP>(h2, s.yb2);
        gemv_acc<10, HP>(h2, h1, &s.yW2[0][0]);
        tanh10(h2);
        bias_init<16>(Y, s.yb3);
        gemv_acc<10, 16>(Y, h2, &s.yW3[0][0]);
    }

    float lc = 0.0f;

    for (int t = 0; t < T_STEPS; t++) {
        float tt = (float)t * DT_F;

        // ---- Zv = MLP_Z([t, X]) ----
        float Zv[16];
        {
            float h1[HP];
            bias_init<HP>(h1, s.zb1);
            gemv_acc<1, HP>(h1, &tt, &s.zW1[0][0]);
            gemv_acc<16, HP>(h1, X, &s.zW1[1][0]);
            tanh10(h1);
            float h2[HP];
            bias_init<HP>(h2, s.zb2);
            gemv_acc<10, HP>(h2, h1, &s.zW2[0][0]);
            tanh10(h2);
            bias_init<16>(Zv, s.zb3);
            gemv_acc<10, 16>(Zv, h2, &s.zW3[0][0]);
        }

        // ---- u = MLP_phi([t, X]) ----
        float u[8];
        {
            float h1[HP];
            bias_init<HP>(h1, s.pb1);
            gemv_acc<1, HP>(h1, &tt, &s.pW1[0][0]);
            gemv_acc<16, HP>(h1, X, &s.pW1[1][0]);
            tanh10(h1);
            float h2[HP];
            bias_init<HP>(h2, s.pb2);
            gemv_acc<10, HP>(h2, h1, &s.pW2[0][0]);
            tanh10(h2);
            bias_init<8>(u, s.pb3);
            gemv_acc<10, 8>(u, h2, &s.pW3[0][0]);
        }

        // ---- drifts / diffusions ----
        float dX[16], fX[16], dY[16];
#pragma unroll
        for (int i = 0; i < 16; i++) { dX[i] = GAMMA_F; fX[i] = SIGMA_F; dY[i] = X[i]; }

        dotrows_acc<16, 16>(dX, X, &s.A[0][0]);   // X @ A^T
        dotrows_acc<8, 16>(dX, u, &s.B[0][0]);    // u @ B^T
        dotrows_acc<16, 16>(fX, X, &s.C[0][0]);   // X @ C^T
        dotrows_acc<8, 16>(fX, u, &s.D[0][0]);    // u @ D^T

        gemv_acc<16, 16>(dY, Y, &s.A[0][0]);      // Y @ A
        gemv_acc<16, 16>(dY, Zv, &s.C[0][0]);     // Zv @ C
        // drift_Y = -dY

        float dH[8];
#pragma unroll
        for (int m = 0; m < 8; m++) dH[m] = u[m];
        gemv_acc<16, 8>(dH, Y, &s.B[0][0]);       // Y @ B
        gemv_acc<16, 8>(dH, Zv, &s.D[0][0]);      // Zv @ D

        float dwi = __ldg(dw + (size_t)t * BATCH + b);

#pragma unroll
        for (int i = 0; i < 16; i++)
            X[i] = fmaf(dwi, fX[i], fmaf(dX[i], DT_F, X[i]));
#pragma unroll
        for (int i = 0; i < 16; i++)
            Y[i] = fmaf(dwi, Zv[i], fmaf(-dY[i], DT_F, Y[i]));

        float ss = 0.0f;
#pragma unroll
        for (int m = 0; m < 8; m++) ss = fmaf(dH[m], dH[m], ss);

        float w = (t == 0 || t == T_STEPS - 1) ? 1.0f : 2.0f;
        lc = fmaf(LC_SCALE * w, ss, lc);
    }

    float lb = 0.0f;
#pragma unroll
    for (int i = 0; i < 16; i++) {
        float d = Y[i] - X[i];
        lb = fmaf(d, d, lb);
    }

    // ---- block reduction (64 threads = 2 warps) ----
#pragma unroll
    for (int o = 16; o; o >>= 1) {
        lb += __shfl_down_sync(0xffffffffu, lb, o);
        lc += __shfl_down_sync(0xffffffffu, lc, o);
    }
    __shared__ float r0[2], r1[2];
    int warp = threadIdx.x >> 5, lane = threadIdx.x & 31;
    if (lane == 0) { r0[warp] = lb; r1[warp] = lc; }
    __syncthreads();
    if (threadIdx.x == 0) {
        g_partial0[blockIdx.x] = r0[0] + r0[1];
        g_partial1[blockIdx.x] = r1[0] + r1[1];
    }
}

// ---------------------------------------------------------------------------
// final reduction: 512 partials -> 2 means
// ---------------------------------------------------------------------------
__global__ void __launch_bounds__(GRID) finalize_kernel(float* __restrict__ out) {
    int tid = threadIdx.x;
    float a = g_partial0[tid];
    float c = g_partial1[tid];
#pragma unroll
    for (int o = 16; o; o >>= 1) {
        a += __shfl_down_sync(0xffffffffu, a, o);
        c += __shfl_down_sync(0xffffffffu, c, o);
    }
    __shared__ float sa[GRID / 32], sc[GRID / 32];
    int warp = tid >> 5, lane = tid & 31;
    if (lane == 0) { sa[warp] = a; sc[warp] = c; }
    __syncthreads();
    if (warp == 0) {
        a = (lane < GRID / 32) ? sa[lane] : 0.0f;
        c = (lane < GRID / 32) ? sc[lane] : 0.0f;
#pragma unroll
        for (int o = 8; o; o >>= 1) {
            a += __shfl_down_sync(0xffffffffu, a, o);
            c += __shfl_down_sync(0xffffffffu, c, o);
        }
        if (lane == 0) {
            out[0] = a * (1.0f / (float)BATCH);
            out[1] = c * (1.0f / (float)BATCH);
        }
    }
}

extern "C" void kernel_launch(void* const* d_in, const int* in_sizes, int n_in,
                              void* d_out, int out_size) {
    const float* dw  = (const float*)d_in[0];
    const float* X0  = (const float*)d_in[1];
    const float* A   = (const float*)d_in[2];
    const float* Bm  = (const float*)d_in[3];
    const float* Cm  = (const float*)d_in[4];
    const float* Dm  = (const float*)d_in[5];
    const float* pW1 = (const float*)d_in[6];
    const float* pb1 = (const float*)d_in[7];
    const float* pW2 = (const float*)d_in[8];
    const float* pb2 = (const float*)d_in[9];
    const float* pW3 = (const float*)d_in[10];
    const float* pb3 = (const float*)d_in[11];
    const float* zW1 = (const float*)d_in[12];
    const float* zb1 = (const float*)d_in[13];
    const float* zW2 = (const float*)d_in[14];
    const float* zb2 = (const float*)d_in[15];
    const float* zW3 = (const float*)d_in[16];
    const float* zb3 = (const float*)d_in[17];
    const float* yW1 = (const float*)d_in[18];
    const float* yb1 = (const float*)d_in[19];
    const float* yW2 = (const float*)d_in[20];
    const float* yb2 = (const float*)d_in[21];
    const float* yW3 = (const float*)d_in[22];
    const float* yb3 = (const float*)d_in[23];

    sim_kernel<<<GRID, BLOCK>>>(dw, X0, A, Bm, Cm, Dm,
                                pW1, pb1, pW2, pb2, pW3, pb3,
                                zW1, zb1, zW2, zb2, zW3, zb3,
                                yW1, yb1, yW2, yb2, yW3, yb3);
    finalize_kernel<<<1, GRID>>>((float*)d_out);
}